// round 2
// baseline (speedup 1.0000x reference)
#include <cuda_runtime.h>
#include <cstdint>
#include <cstddef>

#define BATCH 16
#define D 1024
#define H 16
#define HD 64
#define S 1024
#define TPAST 1023
#define TT 1024
#define FF 4096
#define NV 20
#define NL 3
#define SCALE 0.125f
#define EPS 1e-5f

// ---------------- scratch (no allocation allowed) ----------------
__device__ __align__(16) float g_x[BATCH * D];
__device__ __align__(16) float g_q[BATCH * D];
__device__ __align__(16) float g_k[BATCH * D];
__device__ __align__(16) float g_v[BATCH * D];
__device__ __align__(16) float g_a[BATCH * D];
__device__ __align__(16) float g_t[BATCH * D];
__device__ __align__(16) float g_qkh[BATCH * H * D];
__device__ __align__(16) float g_cb[BATCH * H];
__device__ __align__(16) float g_sc[BATCH * H * S];
__device__ __align__(16) float g_ctx[BATCH * H * D];
__device__ __align__(16) float g_ff[BATCH * FF];

// ---------------- helpers ----------------
__device__ __forceinline__ float block_sum256(float v, float* red) {
    int tid = threadIdx.x;
    #pragma unroll
    for (int o = 16; o; o >>= 1) v += __shfl_down_sync(0xffffffffu, v, o);
    __syncthreads();
    if ((tid & 31) == 0) red[tid >> 5] = v;
    __syncthreads();
    if (tid == 0) {
        float s = red[0];
        #pragma unroll
        for (int i = 1; i < 8; i++) s += red[i];
        red[32] = s;
    }
    __syncthreads();
    return red[32];
}

__device__ __forceinline__ float block_max256(float v, float* red) {
    int tid = threadIdx.x;
    #pragma unroll
    for (int o = 16; o; o >>= 1) v = fmaxf(v, __shfl_down_sync(0xffffffffu, v, o));
    __syncthreads();
    if ((tid & 31) == 0) red[tid >> 5] = v;
    __syncthreads();
    if (tid == 0) {
        float s = red[0];
        #pragma unroll
        for (int i = 1; i < 8; i++) s = fmaxf(s, red[i]);
        red[32] = s;
    }
    __syncthreads();
    return red[32];
}

// out[i] = bias[i % J]   (initialize GEMV outputs with bias; gemv then atomicAdds)
__global__ void set_bias_k(float* __restrict__ out, const float* __restrict__ bias,
                           int J, int total) {
    int i = blockIdx.x * 256 + threadIdx.x;
    if (i < total) out[i] = bias[i % J];
}

// out[b,j] += sum_{i in chunk} in[b,i] * W[i,j]   (W row-major [I,J])
// grid (J/blockDim.x, isplit), atomicAdd into pre-biased out.
template <bool RELU_IN>
__global__ void gemv16_k(const float* __restrict__ in, const float* __restrict__ W,
                         float* __restrict__ out, int I, int J) {
    int j = blockIdx.x * blockDim.x + threadIdx.x;
    int ich = I / gridDim.y;
    int i0 = blockIdx.y * ich;
    __shared__ float xs[BATCH][64];
    float acc[BATCH];
    #pragma unroll
    for (int b = 0; b < BATCH; b++) acc[b] = 0.f;
    for (int ic = i0; ic < i0 + ich; ic += 64) {
        __syncthreads();
        for (int t = threadIdx.x; t < BATCH * 64; t += blockDim.x) {
            int b = t >> 6, ii = t & 63;
            float v = in[b * I + ic + ii];
            if (RELU_IN) v = fmaxf(v, 0.f);
            xs[b][ii] = v;
        }
        __syncthreads();
        #pragma unroll 4
        for (int ii = 0; ii < 64; ii++) {
            float w = W[(size_t)(ic + ii) * J + j];
            #pragma unroll
            for (int b = 0; b < BATCH; b++) acc[b] = fmaf(xs[b][ii], w, acc[b]);
        }
    }
    #pragma unroll
    for (int b = 0; b < BATCH; b++) atomicAdd(&out[b * J + j], acc[b]);
}

// Fused self-attention for one (b,h): scores over 1024 (1023 cached + 1 new),
// softmax, weighted V sum. grid = B*H blocks of 256.
__global__ void self_attn_k(const float* __restrict__ q, const float* __restrict__ knew,
                            const float* __restrict__ vnew, const float* __restrict__ kc,
                            const float* __restrict__ vc, float* __restrict__ out) {
    int b = blockIdx.x >> 4, h = blockIdx.x & 15;
    int tid = threadIdx.x;
    __shared__ __align__(16) float qs[HD];
    __shared__ float sc[TT];
    __shared__ float4 accs[16][16];
    __shared__ float red[33];

    if (tid < HD) qs[tid] = q[b * D + h * HD + tid];
    __syncthreads();

    int g = tid >> 4, l16 = tid & 15;
    size_t base = (size_t)(b * H + h) * TPAST * HD;

    for (int t = g; t < TT; t += 16) {
        const float* kp = (t < TPAST) ? (kc + base + (size_t)t * HD)
                                      : (knew + b * D + h * HD);
        float4 kv = *(const float4*)(kp + l16 * 4);
        float4 qv = *(const float4*)(qs + l16 * 4);
        float p = kv.x * qv.x + kv.y * qv.y + kv.z * qv.z + kv.w * qv.w;
        p += __shfl_down_sync(0xffffffffu, p, 8, 16);
        p += __shfl_down_sync(0xffffffffu, p, 4, 16);
        p += __shfl_down_sync(0xffffffffu, p, 2, 16);
        p += __shfl_down_sync(0xffffffffu, p, 1, 16);
        if (l16 == 0) sc[t] = p * SCALE;
    }
    __syncthreads();

    float m = -1e30f;
    for (int t = tid; t < TT; t += 256) m = fmaxf(m, sc[t]);
    m = block_max256(m, red);

    float s = 0.f;
    for (int t = tid; t < TT; t += 256) {
        float e = __expf(sc[t] - m);
        sc[t] = e;
        s += e;
    }
    s = block_sum256(s, red);   // leading syncthreads also orders sc[] writes
    float inv = 1.f / s;

    float4 acc = {0.f, 0.f, 0.f, 0.f};
    for (int t = g; t < TT; t += 16) {
        const float* vp = (t < TPAST) ? (vc + base + (size_t)t * HD)
                                      : (vnew + b * D + h * HD);
        float4 vv = *(const float4*)(vp + l16 * 4);
        float p = sc[t];
        acc.x = fmaf(p, vv.x, acc.x);
        acc.y = fmaf(p, vv.y, acc.y);
        acc.z = fmaf(p, vv.z, acc.z);
        acc.w = fmaf(p, vv.w, acc.w);
    }
    accs[g][l16] = acc;
    __syncthreads();
    if (tid < 16) {
        float4 s4 = accs[0][tid];
        #pragma unroll
        for (int gg = 1; gg < 16; gg++) {
            float4 o4 = accs[gg][tid];
            s4.x += o4.x; s4.y += o4.y; s4.z += o4.z; s4.w += o4.w;
        }
        s4.x *= inv; s4.y *= inv; s4.z *= inv; s4.w *= inv;
        *((float4*)(out + b * D + h * HD) + tid) = s4;
    }
}

// x = LN(x + a) * g + b    (block per batch row)
__global__ void add_ln_k(float* __restrict__ x, const float* __restrict__ a,
                         const float* __restrict__ gg, const float* __restrict__ bt) {
    int b = blockIdx.x, tid = threadIdx.x;
    __shared__ float red[33];
    float v[4];
    float s = 0.f;
    #pragma unroll
    for (int k = 0; k < 4; k++) {
        int j = k * 256 + tid;
        v[k] = x[b * D + j] + a[b * D + j];
        s += v[k];
    }
    float mean = block_sum256(s, red) * (1.f / D);
    float qv = 0.f;
    #pragma unroll
    for (int k = 0; k < 4; k++) { float dd = v[k] - mean; qv += dd * dd; }
    float var = block_sum256(qv, red) * (1.f / D);
    float rs = rsqrtf(var + EPS);
    #pragma unroll
    for (int k = 0; k < 4; k++) {
        int j = k * 256 + tid;
        x[b * D + j] = (v[k] - mean) * rs * gg[j] + bt[j];
    }
}

// qkh[b,h,d] = sum_hd qc[b,h*64+hd] * wk[d, h*64+hd]   (tiled transpose read of wk)
__global__ void qkh_k(const float* __restrict__ qc, const float* __restrict__ wk,
                      float* __restrict__ qkh) {
    int d0 = blockIdx.x * 64;
    int h = blockIdx.y;
    __shared__ float tile[64][65];
    __shared__ float qs[BATCH][64];
    int tid = threadIdx.x;
    for (int t = tid; t < 64 * 64; t += 256) {
        int r = t >> 6, c = t & 63;
        tile[r][c] = wk[(size_t)(d0 + r) * D + h * 64 + c];
    }
    for (int t = tid; t < BATCH * 64; t += 256) {
        int b = t >> 6, c = t & 63;
        qs[b][c] = qc[b * D + h * 64 + c];
    }
    __syncthreads();
    for (int t = tid; t < BATCH * 64; t += 256) {
        int b = t >> 6, r = t & 63;
        float s = 0.f;
        #pragma unroll 8
        for (int c = 0; c < 64; c++) s = fmaf(tile[r][c], qs[b][c], s);
        qkh[(size_t)(b * H + h) * D + d0 + r] = s;
    }
}

// cb[b,h] = sum_hd qc[b,h*64+hd] * bk[h*64+hd]
__global__ void cb_k(const float* __restrict__ qc, const float* __restrict__ bk,
                     float* __restrict__ cb) {
    int t = threadIdx.x;  // 256 = B*H
    int b = t >> 4, h = t & 15;
    float s = 0.f;
    #pragma unroll 8
    for (int i = 0; i < 64; i++) s = fmaf(qc[b * D + h * 64 + i], bk[h * 64 + i], s);
    cb[t] = s;
}

// sc[b,h,s] = (enc[b,s,:] . qkh[b,h,:] + cb[b,h]) * SCALE   (8 heads per block)
__global__ void cross_scores_k(const float* __restrict__ qkh, const float* __restrict__ cb,
                               const float* __restrict__ enc, float* __restrict__ sc) {
    int b = blockIdx.x, stile = blockIdx.y, hh = blockIdx.z;
    int h0 = hh * 8;
    __shared__ float qs[8][D];
    __shared__ float cbs[8];
    int tid = threadIdx.x;
    for (int t = tid; t < 8 * D; t += 256) {
        int h = t >> 10, d = t & 1023;
        qs[h][d] = qkh[(size_t)(b * H + h0 + h) * D + d];
    }
    if (tid < 8) cbs[tid] = cb[b * H + h0 + tid];
    __syncthreads();
    int warp = tid >> 5, lane = tid & 31;
    for (int s = stile * 128 + warp; s < stile * 128 + 128; s += 8) {
        const float* ep = enc + ((size_t)b * S + s) * D;
        float acc[8];
        #pragma unroll
        for (int h = 0; h < 8; h++) acc[h] = 0.f;
        for (int d = lane; d < D; d += 32) {
            float e = ep[d];
            #pragma unroll
            for (int h = 0; h < 8; h++) acc[h] = fmaf(e, qs[h][d], acc[h]);
        }
        #pragma unroll
        for (int h = 0; h < 8; h++)
            #pragma unroll
            for (int o = 16; o; o >>= 1) acc[h] += __shfl_down_sync(0xffffffffu, acc[h], o);
        if (lane == 0) {
            #pragma unroll
            for (int h = 0; h < 8; h++)
                sc[(size_t)(b * H + h0 + h) * S + s] = (acc[h] + cbs[h]) * SCALE;
        }
    }
}

// in-place softmax over S for each (b,h)
__global__ void softmax_k(float* __restrict__ sc) {
    int bh = blockIdx.x;
    float* p = sc + (size_t)bh * S;
    __shared__ float red[33];
    int tid = threadIdx.x;
    float v[4];
    float m = -1e30f;
    #pragma unroll
    for (int k = 0; k < 4; k++) { v[k] = p[tid + k * 256]; m = fmaxf(m, v[k]); }
    m = block_max256(m, red);
    float s = 0.f;
    #pragma unroll
    for (int k = 0; k < 4; k++) { v[k] = __expf(v[k] - m); s += v[k]; }
    s = block_sum256(s, red);
    float inv = 1.f / s;
    #pragma unroll
    for (int k = 0; k < 4; k++) p[tid + k * 256] = v[k] * inv;
}

// ctx[b,h,d] += sum_s attn[b,h,s] * enc[b,s,d]   (grid: b x dchunk x schunk)
__global__ void ctx_k(const float* __restrict__ attn, const float* __restrict__ enc,
                      float* __restrict__ ctx) {
    int b = blockIdx.x;
    int d = blockIdx.y * 256 + threadIdx.x;
    int sch = S / gridDim.z;
    int s0 = blockIdx.z * sch;
    __shared__ float as[H][64];
    float acc[H];
    #pragma unroll
    for (int h = 0; h < H; h++) acc[h] = 0.f;
    for (int sc0 = s0; sc0 < s0 + sch; sc0 += 64) {
        __syncthreads();
        for (int t = threadIdx.x; t < H * 64; t += 256) {
            int h = t >> 6, ss = t & 63;
            as[h][ss] = attn[(size_t)(b * H + h) * S + sc0 + ss];
        }
        __syncthreads();
        #pragma unroll 4
        for (int ss = 0; ss < 64; ss++) {
            float e = enc[((size_t)b * S + sc0 + ss) * D + d];
            #pragma unroll
            for (int h = 0; h < H; h++) acc[h] = fmaf(as[h][ss], e, acc[h]);
        }
    }
    #pragma unroll
    for (int h = 0; h < H; h++) atomicAdd(&ctx[(size_t)(b * H + h) * D + d], acc[h]);
}

// out[b, h*64+hd] += ctx[b,h,:] . wv[:, h*64+hd]   (per-head GEMV, 4 heads/block)
__global__ void wv_k(const float* __restrict__ ctx, const float* __restrict__ W,
                     float* __restrict__ out) {
    int tid = threadIdx.x;
    int j = blockIdx.x * 256 + tid;
    int hl = tid >> 6;
    int h0 = blockIdx.x * 4;
    int ich = D / gridDim.y;
    int i0 = blockIdx.y * ich;
    __shared__ float cs[BATCH][4][64];
    float acc[BATCH];
    #pragma unroll
    for (int b = 0; b < BATCH; b++) acc[b] = 0.f;
    for (int ic = i0; ic < i0 + ich; ic += 64) {
        __syncthreads();
        for (int t = tid; t < BATCH * 4 * 64; t += 256) {
            int b = t >> 8, h2 = (t >> 6) & 3, ii = t & 63;
            cs[b][h2][ii] = ctx[(size_t)(b * H + h0 + h2) * D + ic + ii];
        }
        __syncthreads();
        #pragma unroll 4
        for (int ii = 0; ii < 64; ii++) {
            float w = W[(size_t)(ic + ii) * D + j];
            #pragma unroll
            for (int b = 0; b < BATCH; b++) acc[b] = fmaf(cs[b][hl][ii], w, acc[b]);
        }
    }
    #pragma unroll
    for (int b = 0; b < BATCH; b++) atomicAdd(&out[b * D + j], acc[b]);
}

// logits[b,v] = x[b,:] . w_out[:,v] + b_out[v]
__global__ void logits_k(const float* __restrict__ x, const float* __restrict__ w,
                         const float* __restrict__ bias, float* __restrict__ out) {
    int b = blockIdx.x, v = blockIdx.y;
    __shared__ float red[33];
    float s = 0.f;
    for (int i = threadIdx.x; i < D; i += 256) s = fmaf(x[b * D + i], w[i * NV + v], s);
    s = block_sum256(s, red);
    if (threadIdx.x == 0) out[b * NV + v] = s + bias[v];
}

// ---------------- host ----------------
extern "C" void kernel_launch(void* const* d_in, const int* in_sizes, int n_in,
                              void* d_out, int out_size) {
    const float* x_in = (const float*)d_in[0];
    const float* enc = (const float*)d_in[1];
    const float* kc = (const float*)d_in[2];
    const float* vc = (const float*)d_in[3];
    const float* wq_s = (const float*)d_in[4];
    const float* bq_s = (const float*)d_in[5];
    const float* wk_s = (const float*)d_in[6];
    const float* bk_s = (const float*)d_in[7];
    const float* wv_s = (const float*)d_in[8];
    const float* bv_s = (const float*)d_in[9];
    const float* wo_s = (const float*)d_in[10];
    const float* bo_s = (const float*)d_in[11];
    const float* wq_c = (const float*)d_in[12];
    const float* bq_c = (const float*)d_in[13];
    const float* wk_c = (const float*)d_in[14];
    const float* bk_c = (const float*)d_in[15];
    const float* wv_c = (const float*)d_in[16];
    const float* bv_c = (const float*)d_in[17];
    const float* wo_c = (const float*)d_in[18];
    const float* bo_c = (const float*)d_in[19];
    const float* w1 = (const float*)d_in[20];
    const float* b1 = (const float*)d_in[21];
    const float* w2 = (const float*)d_in[22];
    const float* b2 = (const float*)d_in[23];
    const float* ln1_g = (const float*)d_in[24];
    const float* ln1_b = (const float*)d_in[25];
    const float* ln2_g = (const float*)d_in[26];
    const float* ln2_b = (const float*)d_in[27];
    const float* ln3_g = (const float*)d_in[28];
    const float* ln3_b = (const float*)d_in[29];
    const float* w_out = (const float*)d_in[30];
    const float* b_out = (const float*)d_in[31];
    float* out = (float*)d_out;

    float *x, *q, *k, *v, *a, *t, *qkh, *cbp, *sc, *ctx, *ff;
    cudaGetSymbolAddress((void**)&x, g_x);
    cudaGetSymbolAddress((void**)&q, g_q);
    cudaGetSymbolAddress((void**)&k, g_k);
    cudaGetSymbolAddress((void**)&v, g_v);
    cudaGetSymbolAddress((void**)&a, g_a);
    cudaGetSymbolAddress((void**)&t, g_t);
    cudaGetSymbolAddress((void**)&qkh, g_qkh);
    cudaGetSymbolAddress((void**)&cbp, g_cb);
    cudaGetSymbolAddress((void**)&sc, g_sc);
    cudaGetSymbolAddress((void**)&ctx, g_ctx);
    cudaGetSymbolAddress((void**)&ff, g_ff);

    cudaMemcpyAsync(x, x_in, (size_t)BATCH * D * sizeof(float),
                    cudaMemcpyDeviceToDevice, 0);

    const int BD = BATCH * D;
    const dim3 gDD(8, 16);  // D->D gemv: J/128 x isplit

    for (int l = 0; l < NL; l++) {
        size_t oD = (size_t)l * D;
        size_t oDD = (size_t)l * D * D;
        size_t cache_off = (size_t)l * BATCH * H * TPAST * HD;

        // ---- self attention ----
        set_bias_k<<<(BD + 255) / 256, 256>>>(q, bq_s + oD, D, BD);
        set_bias_k<<<(BD + 255) / 256, 256>>>(k, bk_s + oD, D, BD);
        set_bias_k<<<(BD + 255) / 256, 256>>>(v, bv_s + oD, D, BD);
        gemv16_k<false><<<gDD, 128>>>(x, wq_s + oDD, q, D, D);
        gemv16_k<false><<<gDD, 128>>>(x, wk_s + oDD, k, D, D);
        gemv16_k<false><<<gDD, 128>>>(x, wv_s + oDD, v, D, D);
        self_attn_k<<<BATCH * H, 256>>>(q, k, v, kc + cache_off, vc + cache_off, a);
        set_bias_k<<<(BD + 255) / 256, 256>>>(t, bo_s + oD, D, BD);
        gemv16_k<false><<<gDD, 128>>>(a, wo_s + oDD, t, D, D);
        add_ln_k<<<BATCH, 256>>>(x, t, ln1_g + oD, ln1_b + oD);

        // ---- cross attention (restructured: no enc@W recompute) ----
        set_bias_k<<<(BD + 255) / 256, 256>>>(q, bq_c + oD, D, BD);
        gemv16_k<false><<<gDD, 128>>>(x, wq_c + oDD, q, D, D);
        qkh_k<<<dim3(16, 16), 256>>>(q, wk_c + oDD, qkh);
        cb_k<<<1, 256>>>(q, bk_c + oD, cbp);
        cross_scores_k<<<dim3(BATCH, 8, 2), 256>>>(qkh, cbp, enc, sc);
        softmax_k<<<BATCH * H, 256>>>(sc);
        cudaMemsetAsync(ctx, 0, (size_t)BATCH * H * D * sizeof(float), 0);
        ctx_k<<<dim3(BATCH, 4, 4), 256>>>(sc, enc, ctx);
        set_bias_k<<<(BD + 255) / 256, 256>>>(a, bv_c + oD, D, BD);
        wv_k<<<dim3(4, 4), 256>>>(ctx, wv_c + oDD, a);
        set_bias_k<<<(BD + 255) / 256, 256>>>(t, bo_c + oD, D, BD);
        gemv16_k<false><<<gDD, 128>>>(a, wo_c + oDD, t, D, D);
        add_ln_k<<<BATCH, 256>>>(x, t, ln2_g + oD, ln2_b + oD);

        // ---- FFN ----
        set_bias_k<<<(BATCH * FF + 255) / 256, 256>>>(ff, b1 + (size_t)l * FF, FF, BATCH * FF);
        gemv16_k<false><<<dim3(32, 8), 128>>>(x, w1 + (size_t)l * D * FF, ff, D, FF);
        set_bias_k<<<(BD + 255) / 256, 256>>>(t, b2 + oD, D, BD);
        gemv16_k<true><<<dim3(8, 32), 128>>>(ff, w2 + (size_t)l * FF * D, t, FF, D);
        add_ln_k<<<BATCH, 256>>>(x, t, ln3_g + oD, ln3_b + oD);
    }

    logits_k<<<dim3(BATCH, NV), 256>>>(x, w_out, b_out, out);
}

// round 6
// speedup vs baseline: 1.4597x; 1.4597x over previous
#include <cuda_runtime.h>
#include <cstdint>
#include <cstddef>

#define BATCH 16
#define D 1024
#define H 16
#define HD 64
#define S 1024
#define TPAST 1023
#define TT 1024
#define FF 4096
#define NV 20
#define NL 3
#define SCALE 0.125f
#define EPS 1e-5f
#define BD (BATCH * D)
#define BHD (BATCH * H * D)

// ---------------- scratch carve (single array, no allocation) ----------------
// zeroed-per-layer region: qs ks vs t1 qc ac t2 t3 (8*BD) + ff (B*FF) + ctx (B*H*D)
#define OFF_QS   0
#define OFF_KS   (1 * BD)
#define OFF_VS   (2 * BD)
#define OFF_T1   (3 * BD)
#define OFF_QC   (4 * BD)
#define OFF_AC   (5 * BD)
#define OFF_T2   (6 * BD)
#define OFF_T3   (7 * BD)
#define OFF_FF   (8 * BD)
#define OFF_CTX  (8 * BD + BATCH * FF)
#define ZTOT     (8 * BD + BATCH * FF + BHD)      /* ctx is B*H*D — was the R5 bug */
#define OFF_X    ZTOT
#define OFF_A    (ZTOT + BD)
#define OFF_QKH  (ZTOT + 2 * BD)
#define OFF_CB   (ZTOT + 2 * BD + BHD)
#define OFF_SC   (ZTOT + 2 * BD + BHD + 256)
#define SCR_TOT  (OFF_SC + BATCH * H * S)

__device__ __align__(16) float g_scr[SCR_TOT];

// ---------------- reductions ----------------
template <int NW>
__device__ __forceinline__ float bsum(float v, float* red) {
    int tid = threadIdx.x;
    #pragma unroll
    for (int o = 16; o; o >>= 1) v += __shfl_down_sync(0xffffffffu, v, o);
    __syncthreads();
    if ((tid & 31) == 0) red[tid >> 5] = v;
    __syncthreads();
    if (tid == 0) {
        float s = red[0];
        #pragma unroll
        for (int i = 1; i < NW; i++) s += red[i];
        red[33] = s;
    }
    __syncthreads();
    return red[33];
}

template <int NW>
__device__ __forceinline__ float bmax(float v, float* red) {
    int tid = threadIdx.x;
    #pragma unroll
    for (int o = 16; o; o >>= 1) v = fmaxf(v, __shfl_down_sync(0xffffffffu, v, o));
    __syncthreads();
    if ((tid & 31) == 0) red[tid >> 5] = v;
    __syncthreads();
    if (tid == 0) {
        float s = red[0];
        #pragma unroll
        for (int i = 1; i < NW; i++) s = fmaxf(s, red[i]);
        red[33] = s;
    }
    __syncthreads();
    return red[33];
}

// ---------------- zero scratch ----------------
__global__ void zero_k(float4* __restrict__ p, int n4) {
    int i = blockIdx.x * 256 + threadIdx.x;
    if (i < n4) p[i] = make_float4(0.f, 0.f, 0.f, 0.f);
}

// ---------------- batched GEMV: out[b,j] (+)= in[b,:]·W[:,j] (+ bias at y==0) ----
// W row-major [I,J]. 128 threads, 4 j-cols per thread (float4 weight loads).
// grid (J/512, I/CH). Split-K partials via atomicAdd into zeroed out.
template <bool RELU, int CH>
__device__ __forceinline__ void gemv_body(const float* __restrict__ in,
                                          const float* __restrict__ W,
                                          const float* __restrict__ bias,
                                          float* __restrict__ out, int I, int J) {
    int j = (blockIdx.x * 128 + threadIdx.x) * 4;
    int i0 = blockIdx.y * CH;
    __shared__ float xs[BATCH][CH];
    for (int t = threadIdx.x; t < BATCH * CH; t += 128) {
        int b = t / CH, ii = t % CH;
        float v = in[b * I + i0 + ii];
        if (RELU) v = fmaxf(v, 0.f);
        xs[b][ii] = v;
    }
    __syncthreads();
    float4 binit = make_float4(0.f, 0.f, 0.f, 0.f);
    if (blockIdx.y == 0) binit = *(const float4*)&bias[j];
    float4 acc[BATCH];
    #pragma unroll
    for (int b = 0; b < BATCH; b++) acc[b] = binit;
    #pragma unroll
    for (int ii = 0; ii < CH; ii++) {
        float4 w = *(const float4*)&W[(size_t)(i0 + ii) * J + j];
        #pragma unroll
        for (int b = 0; b < BATCH; b++) {
            float xv = xs[b][ii];
            acc[b].x = fmaf(xv, w.x, acc[b].x);
            acc[b].y = fmaf(xv, w.y, acc[b].y);
            acc[b].z = fmaf(xv, w.z, acc[b].z);
            acc[b].w = fmaf(xv, w.w, acc[b].w);
        }
    }
    #pragma unroll
    for (int b = 0; b < BATCH; b++) {
        float* o = &out[(size_t)b * J + j];
        atomicAdd(o + 0, acc[b].x);
        atomicAdd(o + 1, acc[b].y);
        atomicAdd(o + 2, acc[b].z);
        atomicAdd(o + 3, acc[b].w);
    }
}

template <bool RELU, int CH>
__global__ void __launch_bounds__(128, 4)
gemv_k(const float* __restrict__ in, const float* __restrict__ W,
       const float* __restrict__ bias, float* __restrict__ out,
       int I, int J) {
    gemv_body<RELU, CH>(in, W, bias, out, I, J);
}

// fused QKV projections: grid.z selects q/k/v
__global__ void __launch_bounds__(128, 4)
gemv_qkv_k(const float* __restrict__ in,
           const float* __restrict__ Wq, const float* __restrict__ Wk,
           const float* __restrict__ Wv,
           const float* __restrict__ bq, const float* __restrict__ bk,
           const float* __restrict__ bv,
           float* __restrict__ q, float* __restrict__ k,
           float* __restrict__ v) {
    int z = blockIdx.z;
    const float* W = (z == 0) ? Wq : (z == 1) ? Wk : Wv;
    const float* bias = (z == 0) ? bq : (z == 1) ? bk : bv;
    float* out = (z == 0) ? q : (z == 1) ? k : v;
    gemv_body<false, 32>(in, W, bias, out, D, D);
}

// ---------------- fused self-attention per (b,h), 512 threads ----------------
__global__ void __launch_bounds__(512)
self_attn_k(const float* __restrict__ q, const float* __restrict__ knew,
            const float* __restrict__ vnew, const float* __restrict__ kc,
            const float* __restrict__ vc, float* __restrict__ out) {
    int b = blockIdx.x >> 4, h = blockIdx.x & 15;
    int tid = threadIdx.x;
    __shared__ __align__(16) float qs[HD];
    __shared__ float sc[TT];
    __shared__ float4 accs[32][16];
    __shared__ float red[34];

    if (tid < HD) qs[tid] = q[b * D + h * HD + tid];
    __syncthreads();

    int g = tid >> 4, l16 = tid & 15;
    size_t base = (size_t)(b * H + h) * TPAST * HD;

    #pragma unroll 4
    for (int t = g; t < TT; t += 32) {
        const float* kp = (t < TPAST) ? (kc + base + (size_t)t * HD)
                                      : (knew + b * D + h * HD);
        float4 kv = *(const float4*)(kp + l16 * 4);
        float4 qv = *(const float4*)(qs + l16 * 4);
        float p = kv.x * qv.x + kv.y * qv.y + kv.z * qv.z + kv.w * qv.w;
        p += __shfl_down_sync(0xffffffffu, p, 8, 16);
        p += __shfl_down_sync(0xffffffffu, p, 4, 16);
        p += __shfl_down_sync(0xffffffffu, p, 2, 16);
        p += __shfl_down_sync(0xffffffffu, p, 1, 16);
        if (l16 == 0) sc[t] = p * SCALE;
    }
    __syncthreads();

    float m = -1e30f;
    #pragma unroll
    for (int t = tid; t < TT; t += 512) m = fmaxf(m, sc[t]);
    m = bmax<16>(m, red);

    float s = 0.f;
    #pragma unroll
    for (int t = tid; t < TT; t += 512) {
        float e = __expf(sc[t] - m);
        sc[t] = e;
        s += e;
    }
    s = bsum<16>(s, red);   // internal syncthreads orders sc[] writes
    float inv = 1.f / s;

    float4 acc = make_float4(0.f, 0.f, 0.f, 0.f);
    #pragma unroll 4
    for (int t = g; t < TT; t += 32) {
        const float* vp = (t < TPAST) ? (vc + base + (size_t)t * HD)
                                      : (vnew + b * D + h * HD);
        float4 vv = *(const float4*)(vp + l16 * 4);
        float p = sc[t];
        acc.x = fmaf(p, vv.x, acc.x);
        acc.y = fmaf(p, vv.y, acc.y);
        acc.z = fmaf(p, vv.z, acc.z);
        acc.w = fmaf(p, vv.w, acc.w);
    }
    accs[g][l16] = acc;
    __syncthreads();
    if (tid < 16) {
        float4 s4 = accs[0][tid];
        #pragma unroll
        for (int gg = 1; gg < 32; gg++) {
            float4 o4 = accs[gg][tid];
            s4.x += o4.x; s4.y += o4.y; s4.z += o4.z; s4.w += o4.w;
        }
        s4.x *= inv; s4.y *= inv; s4.z *= inv; s4.w *= inv;
        *((float4*)(out + b * D + h * HD) + tid) = s4;
    }
}

// ---------------- x = LN(x + a) * g + b ----------------
__global__ void add_ln_k(float* __restrict__ x, const float* __restrict__ a,
                         const float* __restrict__ gg, const float* __restrict__ bt) {
    int b = blockIdx.x, tid = threadIdx.x;
    __shared__ float red[34];
    float v[4];
    float s = 0.f;
    #pragma unroll
    for (int k = 0; k < 4; k++) {
        int j = k * 256 + tid;
        v[k] = x[b * D + j] + a[b * D + j];
        s += v[k];
    }
    float mean = bsum<8>(s, red) * (1.f / D);
    float qv = 0.f;
    #pragma unroll
    for (int k = 0; k < 4; k++) { float dd = v[k] - mean; qv += dd * dd; }
    float var = bsum<8>(qv, red) * (1.f / D);
    float rs = rsqrtf(var + EPS);
    #pragma unroll
    for (int k = 0; k < 4; k++) {
        int j = k * 256 + tid;
        x[b * D + j] = (v[k] - mean) * rs * gg[j] + bt[j];
    }
}

// ---------------- qkh[b,h,d] = q[b,h-slice]·wk[d,h-slice]  (+cb fused) --------
__global__ void qkh_k(const float* __restrict__ qc, const float* __restrict__ wk,
                      const float* __restrict__ bk, float* __restrict__ qkh,
                      float* __restrict__ cb) {
    int d0 = blockIdx.x * 64;
    int h = blockIdx.y;
    __shared__ float tile[64][65];
    __shared__ float qs[BATCH][64];
    int tid = threadIdx.x;
    for (int t = tid; t < 64 * 64; t += 256) {
        int r = t >> 6, c = t & 63;
        tile[r][c] = wk[(size_t)(d0 + r) * D + h * 64 + c];
    }
    for (int t = tid; t < BATCH * 64; t += 256) {
        int b = t >> 6, c = t & 63;
        qs[b][c] = qc[b * D + h * 64 + c];
    }
    __syncthreads();
    for (int t = tid; t < BATCH * 64; t += 256) {
        int b = t >> 6, r = t & 63;
        float s = 0.f;
        #pragma unroll 8
        for (int c = 0; c < 64; c++) s = fmaf(tile[r][c], qs[b][c], s);
        qkh[(size_t)(b * H + h) * D + d0 + r] = s;
    }
    if (blockIdx.x == 0 && tid < BATCH) {
        float s = 0.f;
        #pragma unroll 8
        for (int i = 0; i < 64; i++) s = fmaf(qs[tid][i], bk[h * 64 + i], s);
        cb[tid * H + h] = s;
    }
}

// ---------------- sc[b,h,s] = (enc[b,s,:]·qkh[b,h,:] + cb) * SCALE ------------
__global__ void __launch_bounds__(256)
cross_scores_k(const float* __restrict__ qkh, const float* __restrict__ cb,
               const float* __restrict__ enc, float* __restrict__ sc) {
    int b = blockIdx.x, stile = blockIdx.y, hh = blockIdx.z;
    int h0 = hh * 8;
    __shared__ float qs[8][D];
    __shared__ float cbs[8];
    int tid = threadIdx.x;
    for (int t = tid; t < 8 * D; t += 256) {
        int h = t >> 10, d = t & 1023;
        qs[h][d] = qkh[(size_t)(b * H + h0 + h) * D + d];
    }
    if (tid < 8) cbs[tid] = cb[b * H + h0 + tid];
    __syncthreads();
    int warp = tid >> 5, lane = tid & 31;
    for (int s = stile * 128 + warp; s < stile * 128 + 128; s += 8) {
        const float* ep = enc + ((size_t)b * S + s) * D;
        float acc[8];
        #pragma unroll
        for (int h = 0; h < 8; h++) acc[h] = 0.f;
        for (int d = lane; d < D; d += 32) {
            float e = ep[d];
            #pragma unroll
            for (int h = 0; h < 8; h++) acc[h] = fmaf(e, qs[h][d], acc[h]);
        }
        #pragma unroll
        for (int h = 0; h < 8; h++)
            #pragma unroll
            for (int o = 16; o; o >>= 1) acc[h] += __shfl_down_sync(0xffffffffu, acc[h], o);
        if (lane == 0) {
            #pragma unroll
            for (int h = 0; h < 8; h++)
                sc[(size_t)(b * H + h0 + h) * S + s] = (acc[h] + cbs[h]) * SCALE;
        }
    }
}

// ---------------- softmax over S per (b,h) ----------------
__global__ void softmax_k(float* __restrict__ sc) {
    int bh = blockIdx.x;
    float* p = sc + (size_t)bh * S;
    __shared__ float red[34];
    int tid = threadIdx.x;
    float v[4];
    float m = -1e30f;
    #pragma unroll
    for (int k = 0; k < 4; k++) { v[k] = p[tid + k * 256]; m = fmaxf(m, v[k]); }
    m = bmax<8>(m, red);
    float s = 0.f;
    #pragma unroll
    for (int k = 0; k < 4; k++) { v[k] = __expf(v[k] - m); s += v[k]; }
    s = bsum<8>(s, red);
    float inv = 1.f / s;
    #pragma unroll
    for (int k = 0; k < 4; k++) p[tid + k * 256] = v[k] * inv;
}

// ---------------- ctx[b,h,d] += sum_s attn·enc ----------------
__global__ void __launch_bounds__(256)
ctx_k(const float* __restrict__ attn, const float* __restrict__ enc,
      float* __restrict__ ctx) {
    int b = blockIdx.x;
    int d = blockIdx.y * 256 + threadIdx.x;
    int sch = S / gridDim.z;
    int s0 = blockIdx.z * sch;
    __shared__ float as[H][64];
    float acc[H];
    #pragma unroll
    for (int h = 0; h < H; h++) acc[h] = 0.f;
    for (int sc0 = s0; sc0 < s0 + sch; sc0 += 64) {
        __syncthreads();
        for (int t = threadIdx.x; t < H * 64; t += 256) {
            int h = t >> 6, ss = t & 63;
            as[h][ss] = attn[(size_t)(b * H + h) * S + sc0 + ss];
        }
        __syncthreads();
        #pragma unroll 8
        for (int ss = 0; ss < 64; ss++) {
            float e = enc[((size_t)b * S + sc0 + ss) * D + d];
            #pragma unroll
            for (int h = 0; h < H; h++) acc[h] = fmaf(as[h][ss], e, acc[h]);
        }
    }
    #pragma unroll
    for (int h = 0; h < H; h++) atomicAdd(&ctx[(size_t)(b * H + h) * D + d], acc[h]);
}

// ---------------- out[b,h*64+hd] (+)= ctx[b,h,:]·wv[:,h*64+hd] + bias ---------
__global__ void __launch_bounds__(256)
wv_k(const float* __restrict__ ctx, const float* __restrict__ W,
     const float* __restrict__ bias, float* __restrict__ out) {
    int tid = threadIdx.x;
    int j = blockIdx.x * 256 + tid;
    int hl = tid >> 6;
    int h0 = blockIdx.x * 4;
    int ich = D / gridDim.y;
    int i0 = blockIdx.y * ich;
    __shared__ float cs[BATCH][4][64];
    float binit = (blockIdx.y == 0) ? bias[j] : 0.f;
    float acc[BATCH];
    #pragma unroll
    for (int b = 0; b < BATCH; b++) acc[b] = binit;
    for (int ic = i0; ic < i0 + ich; ic += 64) {
        __syncthreads();
        for (int t = tid; t < BATCH * 4 * 64; t += 256) {
            int b = t >> 8, h2 = (t >> 6) & 3, ii = t & 63;
            cs[b][h2][ii] = ctx[(size_t)(b * H + h0 + h2) * D + ic + ii];
        }
        __syncthreads();
        #pragma unroll 8
        for (int ii = 0; ii < 64; ii++) {
            float w = W[(size_t)(ic + ii) * D + j];
            #pragma unroll
            for (int b = 0; b < BATCH; b++) acc[b] = fmaf(cs[b][hl][ii], w, acc[b]);
        }
    }
    #pragma unroll
    for (int b = 0; b < BATCH; b++) atomicAdd(&out[b * D + j], acc[b]);
}

// ---------------- logits ----------------
__global__ void logits_k(const float* __restrict__ x, const float* __restrict__ w,
                         const float* __restrict__ bias, float* __restrict__ out) {
    int b = blockIdx.x, v = blockIdx.y;
    __shared__ float red[34];
    float s = 0.f;
    for (int i = threadIdx.x; i < D; i += 256) s = fmaf(x[b * D + i], w[i * NV + v], s);
    s = bsum<8>(s, red);
    if (threadIdx.x == 0) out[b * NV + v] = s + bias[v];
}

// ---------------- host ----------------
extern "C" void kernel_launch(void* const* d_in, const int* in_sizes, int n_in,
                              void* d_out, int out_size) {
    const float* x_in = (const float*)d_in[0];
    const float* enc = (const float*)d_in[1];
    const float* kc = (const float*)d_in[2];
    const float* vc = (const float*)d_in[3];
    const float* wq_s = (const float*)d_in[4];
    const float* bq_s = (const float*)d_in[5];
    const float* wk_s = (const float*)d_in[6];
    const float* bk_s = (const float*)d_in[7];
    const float* wv_s = (const float*)d_in[8];
    const float* bv_s = (const float*)d_in[9];
    const float* wo_s = (const float*)d_in[10];
    const float* bo_s = (const float*)d_in[11];
    const float* wq_c = (const float*)d_in[12];
    const float* bq_c = (const float*)d_in[13];
    const float* wk_c = (const float*)d_in[14];
    const float* bk_c = (const float*)d_in[15];
    const float* wv_c = (const float*)d_in[16];
    const float* bv_c = (const float*)d_in[17];
    const float* wo_c = (const float*)d_in[18];
    const float* bo_c = (const float*)d_in[19];
    const float* w1 = (const float*)d_in[20];
    const float* b1 = (const float*)d_in[21];
    const float* w2 = (const float*)d_in[22];
    const float* b2 = (const float*)d_in[23];
    const float* ln1_g = (const float*)d_in[24];
    const float* ln1_b = (const float*)d_in[25];
    const float* ln2_g = (const float*)d_in[26];
    const float* ln2_b = (const float*)d_in[27];
    const float* ln3_g = (const float*)d_in[28];
    const float* ln3_b = (const float*)d_in[29];
    const float* w_out = (const float*)d_in[30];
    const float* b_out = (const float*)d_in[31];
    float* out = (float*)d_out;

    float* scr;
    cudaGetSymbolAddress((void**)&scr, g_scr);
    float* qs = scr + OFF_QS;
    float* ks = scr + OFF_KS;
    float* vs = scr + OFF_VS;
    float* t1 = scr + OFF_T1;
    float* qc = scr + OFF_QC;
    float* ac = scr + OFF_AC;
    float* t2 = scr + OFF_T2;
    float* t3 = scr + OFF_T3;
    float* ff = scr + OFF_FF;
    float* ctx = scr + OFF_CTX;
    float* x = scr + OFF_X;
    float* a = scr + OFF_A;
    float* qkh = scr + OFF_QKH;
    float* cb = scr + OFF_CB;
    float* sc = scr + OFF_SC;

    cudaMemcpyAsync(x, x_in, (size_t)BD * sizeof(float), cudaMemcpyDeviceToDevice, 0);

    const int Z4 = ZTOT / 4;

    for (int l = 0; l < NL; l++) {
        size_t oD = (size_t)l * D;
        size_t oDD = (size_t)l * D * D;
        size_t cache_off = (size_t)l * BATCH * H * TPAST * HD;

        zero_k<<<(Z4 + 255) / 256, 256>>>((float4*)scr, Z4);

        // ---- self attention ----
        gemv_qkv_k<<<dim3(2, 32, 3), 128>>>(x, wq_s + oDD, wk_s + oDD, wv_s + oDD,
                                            bq_s + oD, bk_s + oD, bv_s + oD,
                                            qs, ks, vs);
        self_attn_k<<<BATCH * H, 512>>>(qs, ks, vs, kc + cache_off, vc + cache_off, a);
        gemv_k<false, 32><<<dim3(2, 32), 128>>>(a, wo_s + oDD, bo_s + oD, t1, D, D);
        add_ln_k<<<BATCH, 256>>>(x, t1, ln1_g + oD, ln1_b + oD);

        // ---- cross attention (restructured) ----
        gemv_k<false, 32><<<dim3(2, 32), 128>>>(x, wq_c + oDD, bq_c + oD, qc, D, D);
        qkh_k<<<dim3(16, 16), 256>>>(qc, wk_c + oDD, bk_c + oD, qkh, cb);
        cross_scores_k<<<dim3(BATCH, 8, 2), 256>>>(qkh, cb, enc, sc);
        softmax_k<<<BATCH * H, 256>>>(sc);
        ctx_k<<<dim3(BATCH, 4, 4), 256>>>(sc, enc, ctx);
        wv_k<<<dim3(4, 4), 256>>>(ctx, wv_c + oDD, bv_c + oD, ac);
        gemv_k<false, 32><<<dim3(2, 32), 128>>>(ac, wo_c + oDD, bo_c + oD, t2, D, D);
        add_ln_k<<<BATCH, 256>>>(x, t2, ln2_g + oD, ln2_b + oD);

        // ---- FFN ----
        gemv_k<false, 32><<<dim3(8, 32), 128>>>(x, w1 + (size_t)l * D * FF,
                                                b1 + (size_t)l * FF, ff, D, FF);
        gemv_k<true, 32><<<dim3(2, 128), 128>>>(ff, w2 + (size_t)l * FF * D,
                                                b2 + oD, t3, FF, D);
        add_ln_k<<<BATCH, 256>>>(x, t3, ln3_g + oD, ln3_b + oD);
    }

    logits_k<<<dim3(BATCH, NV), 256>>>(x, w_out, b_out, out);
}

// round 9
// speedup vs baseline: 1.6711x; 1.1448x over previous
#include <cuda_runtime.h>
#include <cstdint>
#include <cstddef>

#define BATCH 16
#define D 1024
#define H 16
#define HD 64
#define S 1024
#define TPAST 1023
#define TT 1024
#define FF 4096
#define NV 20
#define NL 3
#define SCALE 0.125f
#define EPS 1e-5f
#define BD (BATCH * D)
#define BHD (BATCH * H * D)

// ---------------- scratch carve (single array, no allocation) ----------------
#define OFF_QS   0
#define OFF_KS   (1 * BD)
#define OFF_VS   (2 * BD)
#define OFF_T1   (3 * BD)
#define OFF_QC   (4 * BD)
#define OFF_AC   (5 * BD)
#define OFF_T2   (6 * BD)
#define OFF_T3   (7 * BD)
#define OFF_FF   (8 * BD)
#define OFF_CTX  (8 * BD + BATCH * FF)
#define ZTOT     (8 * BD + BATCH * FF + BHD)
#define OFF_X    ZTOT
#define OFF_A    (ZTOT + BD)
#define OFF_QKH  (ZTOT + 2 * BD)
#define OFF_CB   (ZTOT + 2 * BD + BHD)
#define OFF_SC   (ZTOT + 2 * BD + BHD + 256)
#define SCR_TOT  (OFF_SC + BATCH * H * S)

__device__ __align__(16) float g_scr[SCR_TOT];

// ---------------- vectorized global reduction ----------------
__device__ __forceinline__ void red_add_v4(float* p, float4 v) {
    asm volatile("red.global.add.v4.f32 [%0], {%1, %2, %3, %4};"
                 :: "l"(p), "f"(v.x), "f"(v.y), "f"(v.z), "f"(v.w) : "memory");
}

// ---------------- reductions ----------------
template <int NW>
__device__ __forceinline__ float bsum(float v, float* red) {
    int tid = threadIdx.x;
    #pragma unroll
    for (int o = 16; o; o >>= 1) v += __shfl_down_sync(0xffffffffu, v, o);
    __syncthreads();
    if ((tid & 31) == 0) red[tid >> 5] = v;
    __syncthreads();
    if (tid == 0) {
        float s = red[0];
        #pragma unroll
        for (int i = 1; i < NW; i++) s += red[i];
        red[33] = s;
    }
    __syncthreads();
    return red[33];
}

template <int NW>
__device__ __forceinline__ float bmax(float v, float* red) {
    int tid = threadIdx.x;
    #pragma unroll
    for (int o = 16; o; o >>= 1) v = fmaxf(v, __shfl_down_sync(0xffffffffu, v, o));
    __syncthreads();
    if ((tid & 31) == 0) red[tid >> 5] = v;
    __syncthreads();
    if (tid == 0) {
        float s = red[0];
        #pragma unroll
        for (int i = 1; i < NW; i++) s = fmaxf(s, red[i]);
        red[33] = s;
    }
    __syncthreads();
    return red[33];
}

// ---------------- zero scratch ----------------
__global__ void zero_k(float4* __restrict__ p, int n4) {
    int i = blockIdx.x * 256 + threadIdx.x;
    if (i < n4) p[i] = make_float4(0.f, 0.f, 0.f, 0.f);
}

// ---------------- batched GEMV v3: smem-staged W tile ----------------
// Block: 128 threads, 512 cols (4/thread), 16 rows, all 16 batches.
// grid (J/512, I/16). W tile staged via 16 coalesced float4 LDGs/thread.
// Partials committed with red.global.add.v4 into zeroed out (bias folded at y==0).
template <bool RELU>
__device__ __forceinline__ void gemv3_body(const float* __restrict__ in,
                                           const float* __restrict__ W,
                                           const float* __restrict__ bias,
                                           float* __restrict__ out, int I, int J) {
    int tid = threadIdx.x;
    int jb = blockIdx.x * 512;
    int i0 = blockIdx.y * 16;
    __shared__ __align__(16) float wt[16][512];
    __shared__ float xs[BATCH][16];

    #pragma unroll
    for (int r = 0; r < 16; r++)
        *(float4*)&wt[r][tid * 4] =
            *(const float4*)&W[(size_t)(i0 + r) * J + jb + tid * 4];
    #pragma unroll
    for (int t = tid; t < BATCH * 16; t += 128) {
        int b = t >> 4, ii = t & 15;
        float v = in[b * I + i0 + ii];
        if (RELU) v = fmaxf(v, 0.f);
        xs[b][ii] = v;
    }
    __syncthreads();

    float4 binit = make_float4(0.f, 0.f, 0.f, 0.f);
    if (blockIdx.y == 0) binit = *(const float4*)&bias[jb + tid * 4];
    float4 acc[BATCH];
    #pragma unroll
    for (int b = 0; b < BATCH; b++) acc[b] = binit;

    #pragma unroll
    for (int ii = 0; ii < 16; ii++) {
        float4 w = *(const float4*)&wt[ii][tid * 4];
        #pragma unroll
        for (int b = 0; b < BATCH; b++) {
            float xv = xs[b][ii];
            acc[b].x = fmaf(xv, w.x, acc[b].x);
            acc[b].y = fmaf(xv, w.y, acc[b].y);
            acc[b].z = fmaf(xv, w.z, acc[b].z);
            acc[b].w = fmaf(xv, w.w, acc[b].w);
        }
    }
    #pragma unroll
    for (int b = 0; b < BATCH; b++)
        red_add_v4(&out[(size_t)b * J + jb + tid * 4], acc[b]);
}

template <bool RELU>
__global__ void __launch_bounds__(128)
gemv3_k(const float* __restrict__ in, const float* __restrict__ W,
        const float* __restrict__ bias, float* __restrict__ out, int I, int J) {
    gemv3_body<RELU>(in, W, bias, out, I, J);
}

// fused QKV projections: grid.z selects q/k/v
__global__ void __launch_bounds__(128)
gemv3_qkv_k(const float* __restrict__ in,
            const float* __restrict__ Wq, const float* __restrict__ Wk,
            const float* __restrict__ Wv,
            const float* __restrict__ bq, const float* __restrict__ bk,
            const float* __restrict__ bv,
            float* __restrict__ q, float* __restrict__ k,
            float* __restrict__ v) {
    int z = blockIdx.z;
    const float* W = (z == 0) ? Wq : (z == 1) ? Wk : Wv;
    const float* bias = (z == 0) ? bq : (z == 1) ? bk : bv;
    float* out = (z == 0) ? q : (z == 1) ? k : v;
    gemv3_body<false>(in, W, bias, out, D, D);
}

// ---------------- fused self-attention per (b,h), 512 threads ----------------
__global__ void __launch_bounds__(512)
self_attn_k(const float* __restrict__ q, const float* __restrict__ knew,
            const float* __restrict__ vnew, const float* __restrict__ kc,
            const float* __restrict__ vc, float* __restrict__ out) {
    int b = blockIdx.x >> 4, h = blockIdx.x & 15;
    int tid = threadIdx.x;
    __shared__ __align__(16) float qs[HD];
    __shared__ float sc[TT];
    __shared__ float4 accs[32][16];
    __shared__ float red[34];

    if (tid < HD) qs[tid] = q[b * D + h * HD + tid];
    __syncthreads();

    int g = tid >> 4, l16 = tid & 15;
    size_t base = (size_t)(b * H + h) * TPAST * HD;

    #pragma unroll 4
    for (int t = g; t < TT; t += 32) {
        const float* kp = (t < TPAST) ? (kc + base + (size_t)t * HD)
                                      : (knew + b * D + h * HD);
        float4 kv = *(const float4*)(kp + l16 * 4);
        float4 qv = *(const float4*)(qs + l16 * 4);
        float p = kv.x * qv.x + kv.y * qv.y + kv.z * qv.z + kv.w * qv.w;
        p += __shfl_down_sync(0xffffffffu, p, 8, 16);
        p += __shfl_down_sync(0xffffffffu, p, 4, 16);
        p += __shfl_down_sync(0xffffffffu, p, 2, 16);
        p += __shfl_down_sync(0xffffffffu, p, 1, 16);
        if (l16 == 0) sc[t] = p * SCALE;
    }
    __syncthreads();

    float m = -1e30f;
    #pragma unroll
    for (int t = tid; t < TT; t += 512) m = fmaxf(m, sc[t]);
    m = bmax<16>(m, red);

    float s = 0.f;
    #pragma unroll
    for (int t = tid; t < TT; t += 512) {
        float e = __expf(sc[t] - m);
        sc[t] = e;
        s += e;
    }
    s = bsum<16>(s, red);
    float inv = 1.f / s;

    float4 acc = make_float4(0.f, 0.f, 0.f, 0.f);
    #pragma unroll 4
    for (int t = g; t < TT; t += 32) {
        const float* vp = (t < TPAST) ? (vc + base + (size_t)t * HD)
                                      : (vnew + b * D + h * HD);
        float4 vv = *(const float4*)(vp + l16 * 4);
        float p = sc[t];
        acc.x = fmaf(p, vv.x, acc.x);
        acc.y = fmaf(p, vv.y, acc.y);
        acc.z = fmaf(p, vv.z, acc.z);
        acc.w = fmaf(p, vv.w, acc.w);
    }
    accs[g][l16] = acc;
    __syncthreads();
    if (tid < 16) {
        float4 s4 = accs[0][tid];
        #pragma unroll
        for (int gg = 1; gg < 32; gg++) {
            float4 o4 = accs[gg][tid];
            s4.x += o4.x; s4.y += o4.y; s4.z += o4.z; s4.w += o4.w;
        }
        s4.x *= inv; s4.y *= inv; s4.z *= inv; s4.w *= inv;
        *((float4*)(out + b * D + h * HD) + tid) = s4;
    }
}

// ---------------- x = LN(x + a) * g + b ----------------
__global__ void add_ln_k(float* __restrict__ x, const float* __restrict__ a,
                         const float* __restrict__ gg, const float* __restrict__ bt) {
    int b = blockIdx.x, tid = threadIdx.x;
    __shared__ float red[34];
    float v[4];
    float s = 0.f;
    #pragma unroll
    for (int k = 0; k < 4; k++) {
        int j = k * 256 + tid;
        v[k] = x[b * D + j] + a[b * D + j];
        s += v[k];
    }
    float mean = bsum<8>(s, red) * (1.f / D);
    float qv = 0.f;
    #pragma unroll
    for (int k = 0; k < 4; k++) { float dd = v[k] - mean; qv += dd * dd; }
    float var = bsum<8>(qv, red) * (1.f / D);
    float rs = rsqrtf(var + EPS);
    #pragma unroll
    for (int k = 0; k < 4; k++) {
        int j = k * 256 + tid;
        x[b * D + j] = (v[k] - mean) * rs * gg[j] + bt[j];
    }
}

// ---------------- qkh[b,h,d] = q[b,h-slice]·wk[d,h-slice]  (+cb fused) --------
__global__ void qkh_k(const float* __restrict__ qc, const float* __restrict__ wk,
                      const float* __restrict__ bk, float* __restrict__ qkh,
                      float* __restrict__ cb) {
    int d0 = blockIdx.x * 64;
    int h = blockIdx.y;
    __shared__ float tile[64][65];
    __shared__ float qs[BATCH][64];
    int tid = threadIdx.x;
    for (int t = tid; t < 64 * 64; t += 256) {
        int r = t >> 6, c = t & 63;
        tile[r][c] = wk[(size_t)(d0 + r) * D + h * 64 + c];
    }
    for (int t = tid; t < BATCH * 64; t += 256) {
        int b = t >> 6, c = t & 63;
        qs[b][c] = qc[b * D + h * 64 + c];
    }
    __syncthreads();
    for (int t = tid; t < BATCH * 64; t += 256) {
        int b = t >> 6, r = t & 63;
        float s = 0.f;
        #pragma unroll 8
        for (int c = 0; c < 64; c++) s = fmaf(tile[r][c], qs[b][c], s);
        qkh[(size_t)(b * H + h) * D + d0 + r] = s;
    }
    if (blockIdx.x == 0 && tid < BATCH) {
        float s = 0.f;
        #pragma unroll 8
        for (int i = 0; i < 64; i++) s = fmaf(qs[tid][i], bk[h * 64 + i], s);
        cb[tid * H + h] = s;
    }
}

// ---------------- sc[b,h,s] = (enc[b,s,:]·qkh[b,h,:] + cb) * SCALE ------------
__global__ void __launch_bounds__(256)
cross_scores_k(const float* __restrict__ qkh, const float* __restrict__ cb,
               const float* __restrict__ enc, float* __restrict__ sc) {
    int b = blockIdx.x, stile = blockIdx.y, hh = blockIdx.z;
    int h0 = hh * 8;
    __shared__ float qs[8][D];
    __shared__ float cbs[8];
    int tid = threadIdx.x;
    for (int t = tid; t < 8 * D; t += 256) {
        int h = t >> 10, d = t & 1023;
        qs[h][d] = qkh[(size_t)(b * H + h0 + h) * D + d];
    }
    if (tid < 8) cbs[tid] = cb[b * H + h0 + tid];
    __syncthreads();
    int warp = tid >> 5, lane = tid & 31;
    for (int s = stile * 128 + warp; s < stile * 128 + 128; s += 8) {
        const float* ep = enc + ((size_t)b * S + s) * D;
        float acc[8];
        #pragma unroll
        for (int h = 0; h < 8; h++) acc[h] = 0.f;
        for (int d = lane; d < D; d += 32) {
            float e = ep[d];
            #pragma unroll
            for (int h = 0; h < 8; h++) acc[h] = fmaf(e, qs[h][d], acc[h]);
        }
        #pragma unroll
        for (int h = 0; h < 8; h++)
            #pragma unroll
            for (int o = 16; o; o >>= 1) acc[h] += __shfl_down_sync(0xffffffffu, acc[h], o);
        if (lane == 0) {
            #pragma unroll
            for (int h = 0; h < 8; h++)
                sc[(size_t)(b * H + h0 + h) * S + s] = (acc[h] + cbs[h]) * SCALE;
        }
    }
}

// ---------------- softmax over S per (b,h) ----------------
__global__ void softmax_k(float* __restrict__ sc) {
    int bh = blockIdx.x;
    float* p = sc + (size_t)bh * S;
    __shared__ float red[34];
    int tid = threadIdx.x;
    float v[4];
    float m = -1e30f;
    #pragma unroll
    for (int k = 0; k < 4; k++) { v[k] = p[tid + k * 256]; m = fmaxf(m, v[k]); }
    m = bmax<8>(m, red);
    float s = 0.f;
    #pragma unroll
    for (int k = 0; k < 4; k++) { v[k] = __expf(v[k] - m); s += v[k]; }
    s = bsum<8>(s, red);
    float inv = 1.f / s;
    #pragma unroll
    for (int k = 0; k < 4; k++) p[tid + k * 256] = v[k] * inv;
}

// ---------------- ctx[b,h,d] += sum_s attn·enc ----------------
__global__ void __launch_bounds__(256)
ctx_k(const float* __restrict__ attn, const float* __restrict__ enc,
      float* __restrict__ ctx) {
    int b = blockIdx.x;
    int d = blockIdx.y * 256 + threadIdx.x;
    int sch = S / gridDim.z;
    int s0 = blockIdx.z * sch;
    __shared__ float as[H][64];
    float acc[H];
    #pragma unroll
    for (int h = 0; h < H; h++) acc[h] = 0.f;
    for (int sc0 = s0; sc0 < s0 + sch; sc0 += 64) {
        __syncthreads();
        for (int t = threadIdx.x; t < H * 64; t += 256) {
            int h = t >> 6, ss = t & 63;
            as[h][ss] = attn[(size_t)(b * H + h) * S + sc0 + ss];
        }
        __syncthreads();
        #pragma unroll 8
        for (int ss = 0; ss < 64; ss++) {
            float e = enc[((size_t)b * S + sc0 + ss) * D + d];
            #pragma unroll
            for (int h = 0; h < H; h++) acc[h] = fmaf(as[h][ss], e, acc[h]);
        }
    }
    #pragma unroll
    for (int h = 0; h < H; h++) atomicAdd(&ctx[(size_t)(b * H + h) * D + d], acc[h]);
}

// ---------------- out[b,h*64+hd] (+)= ctx[b,h,:]·wv[:,h*64+hd] + bias ---------
__global__ void __launch_bounds__(256)
wv_k(const float* __restrict__ ctx, const float* __restrict__ W,
     const float* __restrict__ bias, float* __restrict__ out) {
    int tid = threadIdx.x;
    int j = blockIdx.x * 256 + tid;
    int hl = tid >> 6;
    int h0 = blockIdx.x * 4;
    int ich = D / gridDim.y;
    int i0 = blockIdx.y * ich;
    __shared__ float cs[BATCH][4][64];
    float binit = (blockIdx.y == 0) ? bias[j] : 0.f;
    float acc[BATCH];
    #pragma unroll
    for (int b = 0; b < BATCH; b++) acc[b] = binit;
    for (int ic = i0; ic < i0 + ich; ic += 64) {
        __syncthreads();
        for (int t = tid; t < BATCH * 4 * 64; t += 256) {
            int b = t >> 8, h2 = (t >> 6) & 3, ii = t & 63;
            cs[b][h2][ii] = ctx[(size_t)(b * H + h0 + h2) * D + ic + ii];
        }
        __syncthreads();
        #pragma unroll 8
        for (int ii = 0; ii < 64; ii++) {
            float w = W[(size_t)(ic + ii) * D + j];
            #pragma unroll
            for (int b = 0; b < BATCH; b++) acc[b] = fmaf(cs[b][hl][ii], w, acc[b]);
        }
    }
    #pragma unroll
    for (int b = 0; b < BATCH; b++) atomicAdd(&out[b * D + j], acc[b]);
}

// ---------------- logits ----------------
__global__ void logits_k(const float* __restrict__ x, const float* __restrict__ w,
                         const float* __restrict__ bias, float* __restrict__ out) {
    int b = blockIdx.x, v = blockIdx.y;
    __shared__ float red[34];
    float s = 0.f;
    for (int i = threadIdx.x; i < D; i += 256) s = fmaf(x[b * D + i], w[i * NV + v], s);
    s = bsum<8>(s, red);
    if (threadIdx.x == 0) out[b * NV + v] = s + bias[v];
}

// ---------------- host ----------------
extern "C" void kernel_launch(void* const* d_in, const int* in_sizes, int n_in,
                              void* d_out, int out_size) {
    const float* x_in = (const float*)d_in[0];
    const float* enc = (const float*)d_in[1];
    const float* kc = (const float*)d_in[2];
    const float* vc = (const float*)d_in[3];
    const float* wq_s = (const float*)d_in[4];
    const float* bq_s = (const float*)d_in[5];
    const float* wk_s = (const float*)d_in[6];
    const float* bk_s = (const float*)d_in[7];
    const float* wv_s = (const float*)d_in[8];
    const float* bv_s = (const float*)d_in[9];
    const float* wo_s = (const float*)d_in[10];
    const float* bo_s = (const float*)d_in[11];
    const float* wq_c = (const float*)d_in[12];
    const float* bq_c = (const float*)d_in[13];
    const float* wk_c = (const float*)d_in[14];
    const float* bk_c = (const float*)d_in[15];
    const float* wv_c = (const float*)d_in[16];
    const float* bv_c = (const float*)d_in[17];
    const float* wo_c = (const float*)d_in[18];
    const float* bo_c = (const float*)d_in[19];
    const float* w1 = (const float*)d_in[20];
    const float* b1 = (const float*)d_in[21];
    const float* w2 = (const float*)d_in[22];
    const float* b2 = (const float*)d_in[23];
    const float* ln1_g = (const float*)d_in[24];
    const float* ln1_b = (const float*)d_in[25];
    const float* ln2_g = (const float*)d_in[26];
    const float* ln2_b = (const float*)d_in[27];
    const float* ln3_g = (const float*)d_in[28];
    const float* ln3_b = (const float*)d_in[29];
    const float* w_out = (const float*)d_in[30];
    const float* b_out = (const float*)d_in[31];
    float* out = (float*)d_out;

    float* scr;
    cudaGetSymbolAddress((void**)&scr, g_scr);
    float* qs = scr + OFF_QS;
    float* ks = scr + OFF_KS;
    float* vs = scr + OFF_VS;
    float* t1 = scr + OFF_T1;
    float* qc = scr + OFF_QC;
    float* ac = scr + OFF_AC;
    float* t2 = scr + OFF_T2;
    float* t3 = scr + OFF_T3;
    float* ff = scr + OFF_FF;
    float* ctx = scr + OFF_CTX;
    float* x = scr + OFF_X;
    float* a = scr + OFF_A;
    float* qkh = scr + OFF_QKH;
    float* cb = scr + OFF_CB;
    float* sc = scr + OFF_SC;

    cudaMemcpyAsync(x, x_in, (size_t)BD * sizeof(float), cudaMemcpyDeviceToDevice, 0);

    const int Z4 = ZTOT / 4;

    for (int l = 0; l < NL; l++) {
        size_t oD = (size_t)l * D;
        size_t oDD = (size_t)l * D * D;
        size_t cache_off = (size_t)l * BATCH * H * TPAST * HD;

        zero_k<<<(Z4 + 255) / 256, 256>>>((float4*)scr, Z4);

        // ---- self attention ----
        gemv3_qkv_k<<<dim3(2, 64, 3), 128>>>(x, wq_s + oDD, wk_s + oDD, wv_s + oDD,
                                             bq_s + oD, bk_s + oD, bv_s + oD,
                                             qs, ks, vs);
        self_attn_k<<<BATCH * H, 512>>>(qs, ks, vs, kc + cache_off, vc + cache_off, a);
        gemv3_k<false><<<dim3(2, 64), 128>>>(a, wo_s + oDD, bo_s + oD, t1, D, D);
        add_ln_k<<<BATCH, 256>>>(x, t1, ln1_g + oD, ln1_b + oD);

        // ---- cross attention (restructured) ----
        gemv3_k<false><<<dim3(2, 64), 128>>>(x, wq_c + oDD, bq_c + oD, qc, D, D);
        qkh_k<<<dim3(16, 16), 256>>>(qc, wk_c + oDD, bk_c + oD, qkh, cb);
        cross_scores_k<<<dim3(BATCH, 8, 2), 256>>>(qkh, cb, enc, sc);
        softmax_k<<<BATCH * H, 256>>>(sc);
        ctx_k<<<dim3(BATCH, 4, 4), 256>>>(sc, enc, ctx);
        wv_k<<<dim3(4, 4), 256>>>(ctx, wv_c + oDD, bv_c + oD, ac);
        gemv3_k<false><<<dim3(2, 64), 128>>>(ac, wo_c + oDD, bo_c + oD, t2, D, D);
        add_ln_k<<<BATCH, 256>>>(x, t2, ln2_g + oD, ln2_b + oD);

        // ---- FFN ----
        gemv3_k<false><<<dim3(8, 64), 128>>>(x, w1 + (size_t)l * D * FF,
                                             b1 + (size_t)l * FF, ff, D, FF);
        gemv3_k<true><<<dim3(2, 256), 128>>>(ff, w2 + (size_t)l * FF * D,
                                             b2 + oD, t3, FF, D);
        add_ln_k<<<BATCH, 256>>>(x, t3, ln3_g + oD, ln3_b + oD);
    }

    logits_k<<<dim3(BATCH, NV), 256>>>(x, w_out, b_out, out);
}